// round 8
// baseline (speedup 1.0000x reference)
#include <cuda_runtime.h>

#define N_NODES 100000
#define F 128
#define SCAN_C 512
#define SCAN_NB ((N_NODES + SCAN_C - 1) / SCAN_C)   // 196

// Scratch (device globals — no runtime allocation allowed)
__device__ float g_agg[N_NODES * F];     // mean-aggregated features (reused both layers)
__device__ float g_h1[N_NODES * F];      // layer-1 output
__device__ int   g_deg[N_NODES];
__device__ int   g_row_start[N_NODES];
__device__ int   g_cursor[N_NODES];
__device__ int   g_blocksum[SCAN_NB];
__device__ int   g_blockoff[SCAN_NB];
__device__ int   g_csr_src[2000000];     // E = 1.6M, padded

// ---------------------------------------------------------------------------
__global__ void deg_zero_kernel() {
    int i = blockIdx.x * blockDim.x + threadIdx.x;
    if (i < N_NODES) g_deg[i] = 0;
}

__global__ void deg_kernel(const int* __restrict__ dst, int E) {
    int i = blockIdx.x * blockDim.x + threadIdx.x;
    if (i < E) atomicAdd(&g_deg[dst[i]], 1);
}

// ---------------------------------------------------------------------------
// Exclusive scan of g_deg -> g_row_start (3 phases)
// ---------------------------------------------------------------------------
__global__ void scan_phaseA() {           // <<<SCAN_NB, SCAN_C>>>
    __shared__ int s[SCAN_C];
    int t = threadIdx.x;
    int i = blockIdx.x * SCAN_C + t;
    s[t] = (i < N_NODES) ? g_deg[i] : 0;
    __syncthreads();
    for (int off = SCAN_C / 2; off > 0; off >>= 1) {
        if (t < off) s[t] += s[t + off];
        __syncthreads();
    }
    if (t == 0) g_blocksum[blockIdx.x] = s[0];
}

__global__ void scan_phaseB() {           // <<<1, 512>>>
    __shared__ int s[512];
    int t = threadIdx.x;
    s[t] = (t < SCAN_NB) ? g_blocksum[t] : 0;
    __syncthreads();
    for (int off = 1; off < 512; off <<= 1) {
        int v = s[t] + ((t >= off) ? s[t - off] : 0);
        __syncthreads();
        s[t] = v;
        __syncthreads();
    }
    if (t < SCAN_NB) g_blockoff[t] = s[t] - g_blocksum[t];  // exclusive
}

__global__ void scan_phaseC() {           // <<<SCAN_NB, SCAN_C>>>
    __shared__ int s[SCAN_C];
    int t = threadIdx.x;
    int i = blockIdx.x * SCAN_C + t;
    int own = (i < N_NODES) ? g_deg[i] : 0;
    s[t] = own;
    __syncthreads();
    for (int off = 1; off < SCAN_C; off <<= 1) {
        int v = s[t] + ((t >= off) ? s[t - off] : 0);
        __syncthreads();
        s[t] = v;
        __syncthreads();
    }
    if (i < N_NODES) {
        int start = g_blockoff[blockIdx.x] + s[t] - own;
        g_row_start[i] = start;
        g_cursor[i] = start;
    }
}

__global__ void fill_kernel(const int* __restrict__ src,
                            const int* __restrict__ dst, int E) {
    int i = blockIdx.x * blockDim.x + threadIdx.x;
    if (i < E) {
        int d = dst[i];
        int pos = atomicAdd(&g_cursor[d], 1);
        g_csr_src[pos] = src[i];
    }
}

// ---------------------------------------------------------------------------
// Gather mean: one warp per dst node, float4 per lane. Unroll x2 for MLP.
// Writes the MEAN directly (1/deg folded in), so GEMM needs no scaling.
// ---------------------------------------------------------------------------
__global__ void gather_kernel(const float* __restrict__ feat) {
    int w = (blockIdx.x * blockDim.x + threadIdx.x) >> 5;
    int lane = threadIdx.x & 31;
    if (w >= N_NODES) return;
    int start = g_row_start[w];
    int deg = g_deg[w];
    float4 acc = make_float4(0.f, 0.f, 0.f, 0.f);
    int e = 0;
    for (; e + 2 <= deg; e += 2) {
        int s0 = g_csr_src[start + e];
        int s1 = g_csr_src[start + e + 1];
        float4 v0 = reinterpret_cast<const float4*>(feat + (size_t)s0 * F)[lane];
        float4 v1 = reinterpret_cast<const float4*>(feat + (size_t)s1 * F)[lane];
        acc.x += v0.x + v1.x; acc.y += v0.y + v1.y;
        acc.z += v0.z + v1.z; acc.w += v0.w + v1.w;
    }
    if (e < deg) {
        int s0 = g_csr_src[start + e];
        float4 v0 = reinterpret_cast<const float4*>(feat + (size_t)s0 * F)[lane];
        acc.x += v0.x; acc.y += v0.y; acc.z += v0.z; acc.w += v0.w;
    }
    float inv = (deg > 0) ? 1.f / (float)deg : 0.f;
    acc.x *= inv; acc.y *= inv; acc.z *= inv; acc.w *= inv;
    reinterpret_cast<float4*>(g_agg + (size_t)w * F)[lane] = acc;
}

// ---------------------------------------------------------------------------
// Fused SAGE GEMM:  out = act( A0 @ Ws + A1 @ Wn + bias )
// Logical K=256 ([A0 | A1] x [Ws ; Wn]).  Tile: 128x128, 8x8/thread,
// double-buffered SMEM.
// ---------------------------------------------------------------------------
__global__ __launch_bounds__(256, 2)
void gemm_kernel(const float* __restrict__ A0, const float* __restrict__ A1,
                 const float* __restrict__ Ws, const float* __restrict__ Wn,
                 const float* __restrict__ bias, float* __restrict__ out,
                 int do_relu) {
    __shared__ float As[2][16][132];   // [buf][k][row]  (transposed A tile)
    __shared__ float Bs[2][16][128];   // [buf][k][col]

    const int tid = threadIdx.x;
    const int tx = tid & 15;           // output-col group
    const int ty = tid >> 4;           // output-row group
    const int row0 = blockIdx.x * 128;

    const int ar0 = tid >> 2;          // A row base (0..63), +64 second half
    const int akq = tid & 3;           // A k-quad
    const int bkr0 = tid >> 5;         // B k-row base (0..7), +8 second half
    const int bcq = tid & 31;          // B col-quad

    float acc[8][8];
#pragma unroll
    for (int i = 0; i < 8; i++)
#pragma unroll
        for (int j = 0; j < 8; j++) acc[i][j] = 0.f;

    float4 pa[2], pb[2];

#define LOAD_CHUNK(c)                                                          \
    {                                                                          \
        const float* Ap = ((c) < 8) ? A0 : A1;                                 \
        const float* Wp = ((c) < 8) ? Ws : Wn;                                 \
        int k0 = ((c) & 7) * 16;                                               \
        _Pragma("unroll")                                                      \
        for (int j = 0; j < 2; j++) {                                          \
            int grow = row0 + ar0 + j * 64;                                    \
            float4 v = make_float4(0.f, 0.f, 0.f, 0.f);                        \
            if (grow < N_NODES)                                                \
                v = *reinterpret_cast<const float4*>(                          \
                        Ap + (size_t)grow * F + k0 + akq * 4);                 \
            pa[j] = v;                                                         \
        }                                                                      \
        _Pragma("unroll")                                                      \
        for (int j = 0; j < 2; j++) {                                          \
            int kr = bkr0 + j * 8;                                             \
            pb[j] = *reinterpret_cast<const float4*>(                          \
                        Wp + (size_t)(k0 + kr) * F + bcq * 4);                 \
        }                                                                      \
    }

#define STORE_CHUNK(buf)                                                       \
    {                                                                          \
        _Pragma("unroll")                                                      \
        for (int j = 0; j < 2; j++) {                                          \
            int row = ar0 + j * 64;                                            \
            As[buf][akq * 4 + 0][row] = pa[j].x;                               \
            As[buf][akq * 4 + 1][row] = pa[j].y;                               \
            As[buf][akq * 4 + 2][row] = pa[j].z;                               \
            As[buf][akq * 4 + 3][row] = pa[j].w;                               \
            int kr = bkr0 + j * 8;                                             \
            *reinterpret_cast<float4*>(&Bs[buf][kr][bcq * 4]) = pb[j];         \
        }                                                                      \
    }

    LOAD_CHUNK(0);
    STORE_CHUNK(0);
    __syncthreads();

    for (int c = 0; c < 16; c++) {
        const int buf = c & 1;
        if (c < 15) LOAD_CHUNK(c + 1);

#pragma unroll
        for (int kk = 0; kk < 16; kk++) {
            float a[8], b[8];
            float4 a0 = *reinterpret_cast<const float4*>(&As[buf][kk][ty * 8]);
            float4 a1 = *reinterpret_cast<const float4*>(&As[buf][kk][ty * 8 + 4]);
            float4 b0 = *reinterpret_cast<const float4*>(&Bs[buf][kk][tx * 8]);
            float4 b1 = *reinterpret_cast<const float4*>(&Bs[buf][kk][tx * 8 + 4]);
            a[0] = a0.x; a[1] = a0.y; a[2] = a0.z; a[3] = a0.w;
            a[4] = a1.x; a[5] = a1.y; a[6] = a1.z; a[7] = a1.w;
            b[0] = b0.x; b[1] = b0.y; b[2] = b0.z; b[3] = b0.w;
            b[4] = b1.x; b[5] = b1.y; b[6] = b1.z; b[7] = b1.w;
#pragma unroll
            for (int i = 0; i < 8; i++)
#pragma unroll
                for (int j = 0; j < 8; j++) acc[i][j] += a[i] * b[j];
        }

        if (c < 15) STORE_CHUNK(buf ^ 1);
        __syncthreads();
    }

    float bv[8];
    {
        float4 v0 = *reinterpret_cast<const float4*>(bias + tx * 8);
        float4 v1 = *reinterpret_cast<const float4*>(bias + tx * 8 + 4);
        bv[0] = v0.x; bv[1] = v0.y; bv[2] = v0.z; bv[3] = v0.w;
        bv[4] = v1.x; bv[5] = v1.y; bv[6] = v1.z; bv[7] = v1.w;
    }
#pragma unroll
    for (int i = 0; i < 8; i++) {
        int grow = row0 + ty * 8 + i;
        if (grow < N_NODES) {
            float r[8];
#pragma unroll
            for (int j = 0; j < 8; j++) {
                float v = acc[i][j] + bv[j];
                r[j] = do_relu ? (v > 0.f ? v : 0.f) : v;
            }
            float* o = out + (size_t)grow * F + tx * 8;
            *reinterpret_cast<float4*>(o)     = make_float4(r[0], r[1], r[2], r[3]);
            *reinterpret_cast<float4*>(o + 4) = make_float4(r[4], r[5], r[6], r[7]);
        }
    }
}

// ---------------------------------------------------------------------------
extern "C" void kernel_launch(void* const* d_in, const int* in_sizes, int n_in,
                              void* d_out, int out_size) {
    const float* x   = (const float*)d_in[0];
    const int*   src = (const int*)d_in[1];    // jnp.int64 downgraded to int32 (x64 disabled)
    const int*   dst = (const int*)d_in[2];
    const float* W1s = (const float*)d_in[3];
    const float* W1n = (const float*)d_in[4];
    const float* b1  = (const float*)d_in[5];
    const float* W2s = (const float*)d_in[6];
    const float* W2n = (const float*)d_in[7];
    const float* b2  = (const float*)d_in[8];
    float* out = (float*)d_out;
    const int E = in_sizes[1];

    float* h1 = nullptr;
    cudaGetSymbolAddress((void**)&h1, g_h1);
    float* agg = nullptr;
    cudaGetSymbolAddress((void**)&agg, g_agg);

    // --- CSR build ---
    deg_zero_kernel<<<(N_NODES + 255) / 256, 256>>>();
    deg_kernel<<<(E + 255) / 256, 256>>>(dst, E);
    scan_phaseA<<<SCAN_NB, SCAN_C>>>();
    scan_phaseB<<<1, 512>>>();
    scan_phaseC<<<SCAN_NB, SCAN_C>>>();
    fill_kernel<<<(E + 255) / 256, 256>>>(src, dst, E);

    const int gather_blocks = (N_NODES * 32 + 255) / 256;
    const int gemm_blocks = (N_NODES + 127) / 128;

    // --- layer 1 ---
    gather_kernel<<<gather_blocks, 256>>>(x);
    gemm_kernel<<<gemm_blocks, 256>>>(x, agg, W1s, W1n, b1, h1, 1);
    // --- layer 2 ---
    gather_kernel<<<gather_blocks, 256>>>(h1);
    gemm_kernel<<<gemm_blocks, 256>>>(h1, agg, W2s, W2n, b2, out, 0);
}

// round 10
// speedup vs baseline: 1.1433x; 1.1433x over previous
#include <cuda_runtime.h>
#include <cstdint>
#include <mma.h>
using namespace nvcuda;

#define N_NODES 100000
#define F 128
#define SCAN_C 512
#define SCAN_NB ((N_NODES + SCAN_C - 1) / SCAN_C)   // 196

// Scratch (device globals — no runtime allocation allowed)
__device__ float g_agg[N_NODES * F];
__device__ float g_h1[N_NODES * F];
__device__ int   g_deg[N_NODES];
__device__ int   g_row_start[N_NODES];
__device__ int   g_cursor[N_NODES];
__device__ int   g_blocksum[SCAN_NB];
__device__ int   g_blockoff[SCAN_NB];
__device__ int   g_csr_src[2000000];

// ---------------------------------------------------------------------------
__global__ void deg_zero_kernel() {
    int i = blockIdx.x * blockDim.x + threadIdx.x;
    if (i < N_NODES) g_deg[i] = 0;
}

__global__ void deg_kernel(const int* __restrict__ dst, int E) {
    int i = blockIdx.x * blockDim.x + threadIdx.x;
    if (i < E) atomicAdd(&g_deg[dst[i]], 1);
}

// --------------------------- CSR scan ---------------------------------------
__global__ void scan_phaseA() {
    __shared__ int s[SCAN_C];
    int t = threadIdx.x;
    int i = blockIdx.x * SCAN_C + t;
    s[t] = (i < N_NODES) ? g_deg[i] : 0;
    __syncthreads();
    for (int off = SCAN_C / 2; off > 0; off >>= 1) {
        if (t < off) s[t] += s[t + off];
        __syncthreads();
    }
    if (t == 0) g_blocksum[blockIdx.x] = s[0];
}

__global__ void scan_phaseB() {
    __shared__ int s[512];
    int t = threadIdx.x;
    s[t] = (t < SCAN_NB) ? g_blocksum[t] : 0;
    __syncthreads();
    for (int off = 1; off < 512; off <<= 1) {
        int v = s[t] + ((t >= off) ? s[t - off] : 0);
        __syncthreads();
        s[t] = v;
        __syncthreads();
    }
    if (t < SCAN_NB) g_blockoff[t] = s[t] - g_blocksum[t];
}

__global__ void scan_phaseC() {
    __shared__ int s[SCAN_C];
    int t = threadIdx.x;
    int i = blockIdx.x * SCAN_C + t;
    int own = (i < N_NODES) ? g_deg[i] : 0;
    s[t] = own;
    __syncthreads();
    for (int off = 1; off < SCAN_C; off <<= 1) {
        int v = s[t] + ((t >= off) ? s[t - off] : 0);
        __syncthreads();
        s[t] = v;
        __syncthreads();
    }
    if (i < N_NODES) {
        int start = g_blockoff[blockIdx.x] + s[t] - own;
        g_row_start[i] = start;
        g_cursor[i] = start;
    }
}

__global__ void fill_kernel(const int* __restrict__ src,
                            const int* __restrict__ dst, int E) {
    int i = blockIdx.x * blockDim.x + threadIdx.x;
    if (i < E) {
        int d = dst[i];
        int pos = atomicAdd(&g_cursor[d], 1);
        g_csr_src[pos] = src[i];
    }
}

// ---------------------------------------------------------------------------
// Gather mean: one warp per dst node, float4 per lane.
// ---------------------------------------------------------------------------
__global__ void gather_kernel(const float* __restrict__ feat) {
    int w = (blockIdx.x * blockDim.x + threadIdx.x) >> 5;
    int lane = threadIdx.x & 31;
    if (w >= N_NODES) return;
    int start = g_row_start[w];
    int deg = g_deg[w];
    float4 acc = make_float4(0.f, 0.f, 0.f, 0.f);
    int e = 0;
    for (; e + 2 <= deg; e += 2) {
        int s0 = g_csr_src[start + e];
        int s1 = g_csr_src[start + e + 1];
        float4 v0 = reinterpret_cast<const float4*>(feat + (size_t)s0 * F)[lane];
        float4 v1 = reinterpret_cast<const float4*>(feat + (size_t)s1 * F)[lane];
        acc.x += v0.x + v1.x; acc.y += v0.y + v1.y;
        acc.z += v0.z + v1.z; acc.w += v0.w + v1.w;
    }
    if (e < deg) {
        int s0 = g_csr_src[start + e];
        float4 v0 = reinterpret_cast<const float4*>(feat + (size_t)s0 * F)[lane];
        acc.x += v0.x; acc.y += v0.y; acc.z += v0.z; acc.w += v0.w;
    }
    float inv = (deg > 0) ? 1.f / (float)deg : 0.f;
    acc.x *= inv; acc.y *= inv; acc.z *= inv; acc.w *= inv;
    reinterpret_cast<float4*>(g_agg + (size_t)w * F)[lane] = acc;
}

// ---------------------------------------------------------------------------
// TF32 tensor-core fused SAGE GEMM: out = act([A0|A1] @ [Ws;Wn] + bias)
// Block 128x128, K=256 in 8 chunks of 32. 8 warps: 4 (M) x 2 (N), each warp
// 32x64 via wmma m16n16k8. cp.async double-buffered SMEM staging.
// Dynamic SMEM arena (70656 B):
//   As [2][128][36] f32  @ 0       (36864 B)   A tile, row-major [row][k]
//   Bs [2][32][132] f32  @ 36864   (33792 B)   W tile, row-major [k][col]
//   Cs [128][132]   f32  @ 0       (67584 B)   epilogue reuse
// ---------------------------------------------------------------------------
#define ARENA_BYTES 70656

__device__ __forceinline__ void cp_async16(uint32_t smem, const void* gptr, int srcsize) {
    asm volatile("cp.async.cg.shared.global [%0], [%1], 16, %2;"
                 :: "r"(smem), "l"(gptr), "r"(srcsize));
}

__global__ __launch_bounds__(256, 2)
void gemm_tc_kernel(const float* __restrict__ A0, const float* __restrict__ A1,
                    const float* __restrict__ Ws, const float* __restrict__ Wn,
                    const float* __restrict__ bias, float* __restrict__ out,
                    int do_relu) {
    extern __shared__ __align__(16) char arena[];
    float* Asf = (float*)arena;              // [2][128][36]
    float* Bsf = (float*)(arena + 36864);    // [2][32][132]
    float* Csf = (float*)arena;              // [128][132]

    const int tid = threadIdx.x;
    const int row0 = blockIdx.x * 128;
    const int w = tid >> 5;
    const int wm = w & 3;        // warp M index (0..3) -> rows wm*32..+32
    const int wn = w >> 2;       // warp N index (0..1) -> cols wn*64..+64

    const uint32_t sA = (uint32_t)__cvta_generic_to_shared(Asf);
    const uint32_t sB = (uint32_t)__cvta_generic_to_shared(Bsf);

    wmma::fragment<wmma::accumulator, 16, 16, 8, float> cfrag[2][4];
#pragma unroll
    for (int i = 0; i < 2; i++)
#pragma unroll
        for (int j = 0; j < 4; j++) wmma::fill_fragment(cfrag[i][j], 0.f);

#define LOAD_CHUNK_TC(c, buf)                                                  \
    {                                                                          \
        const float* Ap = ((c) < 4) ? A0 : A1;                                 \
        const float* Wp = ((c) < 4) ? Ws : Wn;                                 \
        int kb = ((c) & 3) * 32;                                               \
        _Pragma("unroll")                                                      \
        for (int j = 0; j < 4; j++) {                                          \
            int i = tid + j * 256;                                             \
            int row = i >> 3, q = i & 7;                                       \
            int grow = row0 + row;                                             \
            int ok = grow < N_NODES;                                           \
            const float* srcA = Ap + (size_t)(ok ? grow : 0) * F + kb + q * 4; \
            cp_async16(sA + (uint32_t)((buf)*4608 + row * 36 + q * 4) * 4,     \
                       srcA, ok ? 16 : 0);                                     \
            int kr = i >> 5, qq = i & 31;                                      \
            cp_async16(sB + (uint32_t)((buf)*4224 + kr * 132 + qq * 4) * 4,    \
                       Wp + (size_t)(kb + kr) * F + qq * 4, 16);               \
        }                                                                      \
        asm volatile("cp.async.commit_group;");                                \
    }

    LOAD_CHUNK_TC(0, 0);
    asm volatile("cp.async.wait_group 0;");
    __syncthreads();

    for (int c = 0; c < 8; c++) {
        const int buf = c & 1;
        if (c < 7) LOAD_CHUNK_TC(c + 1, buf ^ 1);

#pragma unroll
        for (int ks = 0; ks < 4; ks++) {
            wmma::fragment<wmma::matrix_a, 16, 16, 8, wmma::precision::tf32,
                           wmma::row_major> af[2];
            wmma::fragment<wmma::matrix_b, 16, 16, 8, wmma::precision::tf32,
                           wmma::row_major> bf[4];
#pragma unroll
            for (int i = 0; i < 2; i++) {
                wmma::load_matrix_sync(
                    af[i], Asf + buf * 4608 + (wm * 32 + i * 16) * 36 + ks * 8, 36);
#pragma unroll
                for (int t = 0; t < af[i].num_elements; t++)
                    af[i].x[t] = wmma::__float_to_tf32(af[i].x[t]);
            }
#pragma unroll
            for (int j = 0; j < 4; j++) {
                wmma::load_matrix_sync(
                    bf[j], Bsf + buf * 4224 + (ks * 8) * 132 + wn * 64 + j * 16, 132);
#pragma unroll
                for (int t = 0; t < bf[j].num_elements; t++)
                    bf[j].x[t] = wmma::__float_to_tf32(bf[j].x[t]);
            }
#pragma unroll
            for (int i = 0; i < 2; i++)
#pragma unroll
                for (int j = 0; j < 4; j++)
                    wmma::mma_sync(cfrag[i][j], af[i], bf[j], cfrag[i][j]);
        }

        if (c < 7) asm volatile("cp.async.wait_group 0;");
        __syncthreads();
    }

    // Epilogue: C frags -> SMEM (arena reuse), then bias(+relu) -> global
#pragma unroll
    for (int i = 0; i < 2; i++)
#pragma unroll
        for (int j = 0; j < 4; j++)
            wmma::store_matrix_sync(
                Csf + (wm * 32 + i * 16) * 132 + wn * 64 + j * 16,
                cfrag[i][j], 132, wmma::mem_row_major);
    __syncthreads();

    {
        int r = tid >> 1;
        int half = tid & 1;
        int grow = row0 + r;
        if (grow < N_NODES) {
            float* o = out + (size_t)grow * F + half * 64;
            const float* cs = Csf + r * 132 + half * 64;
            const float* bp = bias + half * 64;
#pragma unroll
            for (int k = 0; k < 16; k++) {
                float4 v = *reinterpret_cast<const float4*>(cs + k * 4);
                float4 b = *reinterpret_cast<const float4*>(bp + k * 4);
                v.x += b.x; v.y += b.y; v.z += b.z; v.w += b.w;
                if (do_relu) {
                    v.x = v.x > 0.f ? v.x : 0.f;
                    v.y = v.y > 0.f ? v.y : 0.f;
                    v.z = v.z > 0.f ? v.z : 0.f;
                    v.w = v.w > 0.f ? v.w : 0.f;
                }
                *reinterpret_cast<float4*>(o + k * 4) = v;
            }
        }
    }
}

// ---------------------------------------------------------------------------
extern "C" void kernel_launch(void* const* d_in, const int* in_sizes, int n_in,
                              void* d_out, int out_size) {
    const float* x   = (const float*)d_in[0];
    const int*   src = (const int*)d_in[1];    // int32 (jax x64 disabled)
    const int*   dst = (const int*)d_in[2];
    const float* W1s = (const float*)d_in[3];
    const float* W1n = (const float*)d_in[4];
    const float* b1  = (const float*)d_in[5];
    const float* W2s = (const float*)d_in[6];
    const float* W2n = (const float*)d_in[7];
    const float* b2  = (const float*)d_in[8];
    float* out = (float*)d_out;
    const int E = in_sizes[1];

    float* h1 = nullptr;
    cudaGetSymbolAddress((void**)&h1, g_h1);
    float* agg = nullptr;
    cudaGetSymbolAddress((void**)&agg, g_agg);

    cudaFuncSetAttribute(gemm_tc_kernel,
                         cudaFuncAttributeMaxDynamicSharedMemorySize, ARENA_BYTES);

    // --- CSR build ---
    deg_zero_kernel<<<(N_NODES + 255) / 256, 256>>>();
    deg_kernel<<<(E + 255) / 256, 256>>>(dst, E);
    scan_phaseA<<<SCAN_NB, SCAN_C>>>();
    scan_phaseB<<<1, 512>>>();
    scan_phaseC<<<SCAN_NB, SCAN_C>>>();
    fill_kernel<<<(E + 255) / 256, 256>>>(src, dst, E);

    const int gather_blocks = (N_NODES * 32 + 255) / 256;
    const int gemm_blocks = (N_NODES + 127) / 128;

    // --- layer 1 ---
    gather_kernel<<<gather_blocks, 256>>>(x);
    gemm_tc_kernel<<<gemm_blocks, 256, ARENA_BYTES>>>(x, agg, W1s, W1n, b1, h1, 1);
    // --- layer 2 ---
    gather_kernel<<<gather_blocks, 256>>>(h1);
    gemm_tc_kernel<<<gemm_blocks, 256, ARENA_BYTES>>>(h1, agg, W2s, W2n, b2, out, 0);
}